// round 1
// baseline (speedup 1.0000x reference)
#include <cuda_runtime.h>
#include <cstdint>

#define B_    8
#define VIN_  4096
#define CIN_  64
#define VOUT_ 16384
#define S_    9
#define COUT_ 32

// 32 MB scratch for pooled[b][v][c]
__device__ float g_pooled[(size_t)B_ * VOUT_ * CIN_];

// ---------------------------------------------------------------------------
// Kernel 1: pooled[b,v,:] = sum_{j<3} trans_value[e_j] * x[b, trans_col[e_j], :]
//           where e_j = row_map[v, j]
// Block = 256 threads = 16 v's, 16 threads (float4) per row, loop over b.
// ---------------------------------------------------------------------------
__global__ __launch_bounds__(256) void pool_kernel(
    const float* __restrict__ x,
    const int*   __restrict__ trans_col,
    const float* __restrict__ trans_value,
    const int*   __restrict__ row_map)
{
    __shared__ int   col_s[16][3];
    __shared__ float val_s[16][3];

    const int tid  = threadIdx.x;
    const int vloc = tid >> 4;      // 0..15
    const int quad = tid & 15;      // 0..15 -> float4 lane within the 64-ch row
    const int v    = blockIdx.x * 16 + vloc;

    if (quad < 3) {
        const int e = row_map[v * 3 + quad];
        col_s[vloc][quad] = trans_col[e];
        val_s[vloc][quad] = trans_value[e];
    }
    __syncthreads();

    const int c0 = quad * 4;
    const int col0 = col_s[vloc][0];
    const int col1 = col_s[vloc][1];
    const int col2 = col_s[vloc][2];
    const float w0 = val_s[vloc][0];
    const float w1 = val_s[vloc][1];
    const float w2 = val_s[vloc][2];

#pragma unroll
    for (int b = 0; b < B_; b++) {
        const float4 a0 = *(const float4*)(x + ((size_t)(b * VIN_ + col0)) * CIN_ + c0);
        const float4 a1 = *(const float4*)(x + ((size_t)(b * VIN_ + col1)) * CIN_ + c0);
        const float4 a2 = *(const float4*)(x + ((size_t)(b * VIN_ + col2)) * CIN_ + c0);
        float4 r;
        r.x = fmaf(w0, a0.x, fmaf(w1, a1.x, w2 * a2.x));
        r.y = fmaf(w0, a0.y, fmaf(w1, a1.y, w2 * a2.y));
        r.z = fmaf(w0, a0.z, fmaf(w1, a1.z, w2 * a2.z));
        r.w = fmaf(w0, a0.w, fmaf(w1, a1.w, w2 * a2.w));
        *(float4*)(g_pooled + ((size_t)(b * VOUT_ + v)) * CIN_ + c0) = r;
    }
}

// ---------------------------------------------------------------------------
// Kernel 2: per (b, v):
//   dw[c]  = bd[c] + sum_s Wd[c,s] * pooled[b, indices[v,s], c]
//   out[o] = relu( bp[o] + sum_c Wp[o,c] * dw[c] )
// One warp per v; loop over b (amortizes metadata + weight registers).
// Lane owns channel pair (2l, 2l+1) for the depthwise stage, and output o=lane
// for the pointwise stage (dw exchanged via smem, broadcast float4 reads).
// ---------------------------------------------------------------------------
__global__ __launch_bounds__(256) void fused_conv_kernel(
    const int*   __restrict__ indices,
    const float* __restrict__ Wd,
    const float* __restrict__ bd,
    const float* __restrict__ Wp,
    const float* __restrict__ bp,
    float*       __restrict__ out)
{
    __shared__ float dw_s[8][CIN_];

    const int tid  = threadIdx.x;
    const int warp = tid >> 5;
    const int lane = tid & 31;
    const int v    = blockIdx.x * 8 + warp;

    // neighbor indices: 1 load per lane (<9), broadcast by shuffle
    int u_reg = 0;
    if (lane < S_) u_reg = indices[v * S_ + lane];
    int u[S_];
#pragma unroll
    for (int s = 0; s < S_; s++) u[s] = __shfl_sync(0xffffffffu, u_reg, s);

    // depthwise weights for this lane's channel pair
    const int ca = 2 * lane;
    const int cb = 2 * lane + 1;
    float wda[S_], wdb[S_];
#pragma unroll
    for (int s = 0; s < S_; s++) {
        wda[s] = __ldg(Wd + ca * S_ + s);
        wdb[s] = __ldg(Wd + cb * S_ + s);
    }
    const float bda = __ldg(bd + ca);
    const float bdb = __ldg(bd + cb);

    // pointwise weights for output o = lane
    float wp[CIN_];
#pragma unroll
    for (int c = 0; c < CIN_; c++) wp[c] = __ldg(Wp + lane * CIN_ + c);
    const float bpo = __ldg(bp + lane);

    float* dw = dw_s[warp];

#pragma unroll
    for (int b = 0; b < B_; b++) {
        float accx = bda, accy = bdb;
#pragma unroll
        for (int s = 0; s < S_; s++) {
            const float2 p =
                *(const float2*)(g_pooled + ((size_t)(b * VOUT_ + u[s])) * CIN_ + ca);
            accx = fmaf(wda[s], p.x, accx);
            accy = fmaf(wdb[s], p.y, accy);
        }
        ((float2*)dw)[lane] = make_float2(accx, accy);
        __syncwarp();

        float acc = bpo;
#pragma unroll
        for (int c = 0; c < CIN_; c += 4) {
            const float4 d4 = *(const float4*)(dw + c);
            acc = fmaf(wp[c + 0], d4.x, acc);
            acc = fmaf(wp[c + 1], d4.y, acc);
            acc = fmaf(wp[c + 2], d4.z, acc);
            acc = fmaf(wp[c + 3], d4.w, acc);
        }
        out[((size_t)(b * VOUT_ + v)) * COUT_ + lane] = fmaxf(acc, 0.0f);
        __syncwarp();   // protect dw before next b overwrites it
    }
}

// ---------------------------------------------------------------------------
// Launch. Input order (metadata.txt): x, trans_row(unused), trans_col,
// trans_value, row_map, indices, Wd, bd, Wp, bp. Output float32 (8,16384,32).
// ---------------------------------------------------------------------------
extern "C" void kernel_launch(void* const* d_in, const int* in_sizes, int n_in,
                              void* d_out, int out_size)
{
    const float* x           = (const float*)d_in[0];
    const int*   trans_col   = (const int*)  d_in[2];
    const float* trans_value = (const float*)d_in[3];
    const int*   row_map     = (const int*)  d_in[4];
    const int*   indices     = (const int*)  d_in[5];
    const float* Wd          = (const float*)d_in[6];
    const float* bd          = (const float*)d_in[7];
    const float* Wp          = (const float*)d_in[8];
    const float* bp          = (const float*)d_in[9];
    float* out = (float*)d_out;

    pool_kernel<<<VOUT_ / 16, 256>>>(x, trans_col, trans_value, row_map);
    fused_conv_kernel<<<VOUT_ / 8, 256>>>(indices, Wd, bd, Wp, bp, out);
}

// round 3
// speedup vs baseline: 2.8226x; 2.8226x over previous
#include <cuda_runtime.h>
#include <cstdint>

#define B_    8
#define VIN_  4096
#define CIN_  64
#define VOUT_ 16384
#define S_    9
#define COUT_ 32

// 32 MB scratch for pooled[b][v][c]
__device__ float g_pooled[(size_t)B_ * VOUT_ * CIN_];

// ---------------------------------------------------------------------------
// Kernel 1: pooled[b,v,:] = sum_{j<3} trans_value[e_j] * x[b, trans_col[e_j], :]
// ---------------------------------------------------------------------------
__global__ __launch_bounds__(256) void pool_kernel(
    const float* __restrict__ x,
    const int*   __restrict__ trans_col,
    const float* __restrict__ trans_value,
    const int*   __restrict__ row_map)
{
    __shared__ int   col_s[16][3];
    __shared__ float val_s[16][3];

    const int tid  = threadIdx.x;
    const int vloc = tid >> 4;      // 0..15
    const int quad = tid & 15;      // float4 lane within the 64-ch row
    const int v    = blockIdx.x * 16 + vloc;

    if (quad < 3) {
        const int e = row_map[v * 3 + quad];
        col_s[vloc][quad] = trans_col[e];
        val_s[vloc][quad] = trans_value[e];
    }
    __syncthreads();

    const int c0 = quad * 4;
    const int col0 = col_s[vloc][0];
    const int col1 = col_s[vloc][1];
    const int col2 = col_s[vloc][2];
    const float w0 = val_s[vloc][0];
    const float w1 = val_s[vloc][1];
    const float w2 = val_s[vloc][2];

#pragma unroll
    for (int b = 0; b < B_; b++) {
        const float4 a0 = *(const float4*)(x + ((size_t)(b * VIN_ + col0)) * CIN_ + c0);
        const float4 a1 = *(const float4*)(x + ((size_t)(b * VIN_ + col1)) * CIN_ + c0);
        const float4 a2 = *(const float4*)(x + ((size_t)(b * VIN_ + col2)) * CIN_ + c0);
        float4 r;
        r.x = fmaf(w0, a0.x, fmaf(w1, a1.x, w2 * a2.x));
        r.y = fmaf(w0, a0.y, fmaf(w1, a1.y, w2 * a2.y));
        r.z = fmaf(w0, a0.z, fmaf(w1, a1.z, w2 * a2.z));
        r.w = fmaf(w0, a0.w, fmaf(w1, a1.w, w2 * a2.w));
        *(float4*)(g_pooled + ((size_t)(b * VOUT_ + v)) * CIN_ + c0) = r;
    }
}

// ---------------------------------------------------------------------------
// Kernel 2: one warp per v, two phases.
//  Phase 1 (depthwise): all 8 b's, 72 independent gathers, results into
//                       dw_s[warp][b][64] (lane owns channels 2l, 2l+1).
//  Phase 2 (pointwise): lane = output o; 8 accumulators; Wp read from padded
//                       smem [32][68] (conflict-free LDS.128).
// ---------------------------------------------------------------------------
#define WARPS_PER_BLOCK 8
#define WP_PAD 68   // 64 + 4 pad: float4-aligned, bank pattern (4*lane+c)%32

__global__ __launch_bounds__(256) void fused_conv_kernel(
    const int*   __restrict__ indices,
    const float* __restrict__ Wd,
    const float* __restrict__ bd,
    const float* __restrict__ Wp,
    const float* __restrict__ bp,
    float*       __restrict__ out)
{
    __shared__ float dw_s[WARPS_PER_BLOCK][B_][CIN_];   // 16 KB
    __shared__ float wp_s[COUT_][WP_PAD];               // 8.7 KB

    const int tid  = threadIdx.x;
    const int warp = tid >> 5;
    const int lane = tid & 31;
    const int v    = blockIdx.x * WARPS_PER_BLOCK + warp;

    // cooperative load of Wp into padded smem
    for (int i = tid; i < COUT_ * CIN_; i += 256) {
        wp_s[i >> 6][i & 63] = Wp[i];
    }

    // neighbor indices: one load per lane (<9), broadcast by shuffle
    int u_reg = 0;
    if (lane < S_) u_reg = indices[v * S_ + lane];
    int u[S_];
#pragma unroll
    for (int s = 0; s < S_; s++) u[s] = __shfl_sync(0xffffffffu, u_reg, s);

    // ---------------- Phase 1: depthwise for all 8 b ----------------
    {
        const int ca = 2 * lane;
        float wda[S_], wdb[S_];
#pragma unroll
        for (int s = 0; s < S_; s++) {
            wda[s] = __ldg(Wd + ca * S_ + s);
            wdb[s] = __ldg(Wd + (ca + 1) * S_ + s);
        }
        const float bda = __ldg(bd + ca);
        const float bdb = __ldg(bd + ca + 1);

#pragma unroll
        for (int b = 0; b < B_; b++) {
            float accx = bda, accy = bdb;
#pragma unroll
            for (int s = 0; s < S_; s++) {
                const float2 p =
                    *(const float2*)(g_pooled + ((size_t)(b * VOUT_ + u[s])) * CIN_ + ca);
                accx = fmaf(wda[s], p.x, accx);
                accy = fmaf(wdb[s], p.y, accy);
            }
            *(float2*)&dw_s[warp][b][ca] = make_float2(accx, accy);
        }
    }
    __syncthreads();   // wp_s ready + dw_s visible across lanes of each warp

    // ---------------- Phase 2: pointwise, lane = output o ----------------
    float acc[B_];
    const float bpo = __ldg(bp + lane);
#pragma unroll
    for (int b = 0; b < B_; b++) acc[b] = bpo;

#pragma unroll
    for (int c4 = 0; c4 < CIN_ / 4; c4++) {
        const float4 w4 = *(const float4*)&wp_s[lane][c4 * 4];
#pragma unroll
        for (int b = 0; b < B_; b++) {
            const float4 d4 = *(const float4*)&dw_s[warp][b][c4 * 4];
            acc[b] = fmaf(w4.x, d4.x, acc[b]);
            acc[b] = fmaf(w4.y, d4.y, acc[b]);
            acc[b] = fmaf(w4.z, d4.z, acc[b]);
            acc[b] = fmaf(w4.w, d4.w, acc[b]);
        }
    }

#pragma unroll
    for (int b = 0; b < B_; b++) {
        out[((size_t)(b * VOUT_ + v)) * COUT_ + lane] = fmaxf(acc[b], 0.0f);
    }
}

// ---------------------------------------------------------------------------
// Launch. Input order: x, trans_row(unused), trans_col, trans_value, row_map,
// indices, Wd, bd, Wp, bp. Output float32 (8,16384,32).
// ---------------------------------------------------------------------------
extern "C" void kernel_launch(void* const* d_in, const int* in_sizes, int n_in,
                              void* d_out, int out_size)
{
    const float* x           = (const float*)d_in[0];
    const int*   trans_col   = (const int*)  d_in[2];
    const float* trans_value = (const float*)d_in[3];
    const int*   row_map     = (const int*)  d_in[4];
    const int*   indices     = (const int*)  d_in[5];
    const float* Wd          = (const float*)d_in[6];
    const float* bd          = (const float*)d_in[7];
    const float* Wp          = (const float*)d_in[8];
    const float* bp          = (const float*)d_in[9];
    float* out = (float*)d_out;

    pool_kernel<<<VOUT_ / 16, 256>>>(x, trans_col, trans_value, row_map);
    fused_conv_kernel<<<VOUT_ / WARPS_PER_BLOCK, 256>>>(indices, Wd, bd, Wp, bp, out);
}

// round 8
// speedup vs baseline: 3.0386x; 1.0765x over previous
#include <cuda_runtime.h>
#include <cstdint>

#define B_    8
#define VIN_  4096
#define CIN_  64
#define VOUT_ 16384
#define S_    9
#define COUT_ 32

// 32 MB scratch for pooled[b][v][c]
__device__ float g_pooled[(size_t)B_ * VOUT_ * CIN_];

// ---------------- packed f32x2 helpers (Blackwell FFMA2) ----------------
__device__ __forceinline__ unsigned long long pack2(float lo, float hi) {
    unsigned long long r;
    asm("mov.b64 %0, {%1, %2};" : "=l"(r) : "f"(lo), "f"(hi));
    return r;
}
__device__ __forceinline__ void fma2(unsigned long long& d,
                                     unsigned long long a,
                                     unsigned long long b) {
    asm("fma.rn.f32x2 %0, %1, %2, %0;" : "+l"(d) : "l"(a), "l"(b));
}
__device__ __forceinline__ float2 unpack2(unsigned long long v) {
    float2 r;
    asm("mov.b64 {%0, %1}, %2;" : "=f"(r.x), "=f"(r.y) : "l"(v));
    return r;
}

// ---------------------------------------------------------------------------
// Kernel 1: pooled[b,v,:] = sum_{j<3} trans_value[e_j] * x[b, trans_col[e_j], :]
// ---------------------------------------------------------------------------
__global__ __launch_bounds__(256) void pool_kernel(
    const float* __restrict__ x,
    const int*   __restrict__ trans_col,
    const float* __restrict__ trans_value,
    const int*   __restrict__ row_map)
{
    __shared__ int   col_s[16][3];
    __shared__ float val_s[16][3];

    const int tid  = threadIdx.x;
    const int vloc = tid >> 4;
    const int quad = tid & 15;
    const int v    = blockIdx.x * 16 + vloc;

    if (quad < 3) {
        const int e = row_map[v * 3 + quad];
        col_s[vloc][quad] = trans_col[e];
        val_s[vloc][quad] = trans_value[e];
    }
    __syncthreads();

    const int c0 = quad * 4;
    const int col0 = col_s[vloc][0];
    const int col1 = col_s[vloc][1];
    const int col2 = col_s[vloc][2];
    const float w0 = val_s[vloc][0];
    const float w1 = val_s[vloc][1];
    const float w2 = val_s[vloc][2];

#pragma unroll
    for (int b = 0; b < B_; b++) {
        const float4 a0 = *(const float4*)(x + ((size_t)(b * VIN_ + col0)) * CIN_ + c0);
        const float4 a1 = *(const float4*)(x + ((size_t)(b * VIN_ + col1)) * CIN_ + c0);
        const float4 a2 = *(const float4*)(x + ((size_t)(b * VIN_ + col2)) * CIN_ + c0);
        float4 r;
        r.x = fmaf(w0, a0.x, fmaf(w1, a1.x, w2 * a2.x));
        r.y = fmaf(w0, a0.y, fmaf(w1, a1.y, w2 * a2.y));
        r.z = fmaf(w0, a0.z, fmaf(w1, a1.z, w2 * a2.z));
        r.w = fmaf(w0, a0.w, fmaf(w1, a1.w, w2 * a2.w));
        *(float4*)(g_pooled + ((size_t)(b * VOUT_ + v)) * CIN_ + c0) = r;
    }
}

// ---------------------------------------------------------------------------
// Kernel 2: one warp per v, two phases.
//   Phase 1 (depthwise): lane owns channels (2l, 2l+1) as an f32x2 pair;
//     72 independent LDG.64 gathers; results transposed into
//     dw_s[warp][c][b] (stride 12 floats -> 16B-aligned b-quads, <=2-way STS).
//   Phase 2 (pointwise): lane = output o; acc[8 b] as 4 f32x2;
//     d operands read as ulonglong2 (LDS.128 broadcast, pre-paired over b),
//     Wp from padded smem (conflict-free LDS.128), FFMA2 throughout.
// ---------------------------------------------------------------------------
#define WARPS_PER_BLOCK 8
#define WP_PAD    68   // 64 + 4 pad, conflict-free LDS.128
#define DW_STRIDE 12   // floats per channel row: 48B -> aligned quads

__global__ __launch_bounds__(256, 4) void fused_conv_kernel(
    const int*   __restrict__ indices,
    const float* __restrict__ Wd,
    const float* __restrict__ bd,
    const float* __restrict__ Wp,
    const float* __restrict__ bp,
    float*       __restrict__ out)
{
    __shared__ float dw_s[WARPS_PER_BLOCK][CIN_][DW_STRIDE];  // 24 KB
    __shared__ float wp_s[COUT_][WP_PAD];                     // 8.7 KB

    const int tid  = threadIdx.x;
    const int warp = tid >> 5;
    const int lane = tid & 31;
    const int v    = blockIdx.x * WARPS_PER_BLOCK + warp;

    // cooperative load of Wp into padded smem [o][c]
    for (int i = tid; i < COUT_ * CIN_; i += 256) {
        wp_s[i >> 6][i & 63] = Wp[i];
    }

    // neighbor indices: one load per lane (<9), broadcast by shuffle
    int u_reg = 0;
    if (lane < S_) u_reg = indices[v * S_ + lane];
    int u[S_];
#pragma unroll
    for (int s = 0; s < S_; s++) u[s] = __shfl_sync(0xffffffffu, u_reg, s);

    // ---------------- Phase 1: depthwise, packed over channel pair ----------
    {
        const int ca = 2 * lane;
        unsigned long long wdp[S_];
#pragma unroll
        for (int s = 0; s < S_; s++) {
            wdp[s] = pack2(__ldg(Wd + ca * S_ + s), __ldg(Wd + (ca + 1) * S_ + s));
        }
        const unsigned long long bdp = pack2(__ldg(bd + ca), __ldg(bd + ca + 1));

#pragma unroll
        for (int half = 0; half < 2; half++) {
            unsigned long long acc[4];
#pragma unroll
            for (int j = 0; j < 4; j++) acc[j] = bdp;

#pragma unroll
            for (int j = 0; j < 4; j++) {
                const int b = half * 4 + j;
#pragma unroll
                for (int s = 0; s < S_; s++) {
                    const unsigned long long p = *(const unsigned long long*)(
                        g_pooled + ((size_t)(b * VOUT_ + u[s])) * CIN_ + ca);
                    fma2(acc[j], wdp[s], p);
                }
            }

            // transpose into [c][b] quads
            const float2 a0 = unpack2(acc[0]);
            const float2 a1 = unpack2(acc[1]);
            const float2 a2 = unpack2(acc[2]);
            const float2 a3 = unpack2(acc[3]);
            float4 fx, fy;
            fx.x = a0.x; fx.y = a1.x; fx.z = a2.x; fx.w = a3.x;
            fy.x = a0.y; fy.y = a1.y; fy.z = a2.y; fy.w = a3.y;
            *(float4*)&dw_s[warp][ca][half * 4]     = fx;
            *(float4*)&dw_s[warp][ca + 1][half * 4] = fy;
        }
    }
    __syncthreads();   // wp_s ready + dw_s visible within warp

    // ---------------- Phase 2: pointwise, lane = output o --------------------
    const float bpo = __ldg(bp + lane);
    unsigned long long acc01 = pack2(bpo, bpo);
    unsigned long long acc23 = acc01, acc45 = acc01, acc67 = acc01;

#pragma unroll
    for (int c4 = 0; c4 < CIN_ / 4; c4++) {
        const float4 w4 = *(const float4*)&wp_s[lane][c4 * 4];
        const unsigned long long ww0 = pack2(w4.x, w4.x);
        const unsigned long long ww1 = pack2(w4.y, w4.y);
        const unsigned long long ww2 = pack2(w4.z, w4.z);
        const unsigned long long ww3 = pack2(w4.w, w4.w);

#pragma unroll
        for (int j = 0; j < 4; j++) {
            const int c = c4 * 4 + j;
            const ulonglong2 dlo = *(const ulonglong2*)&dw_s[warp][c][0]; // b0..3
            const ulonglong2 dhi = *(const ulonglong2*)&dw_s[warp][c][4]; // b4..7
            const unsigned long long w =
                (j == 0) ? ww0 : (j == 1) ? ww1 : (j == 2) ? ww2 : ww3;
            fma2(acc01, w, dlo.x);
            fma2(acc23, w, dlo.y);
            fma2(acc45, w, dhi.x);
            fma2(acc67, w, dhi.y);
        }
    }

    const float2 r01 = unpack2(acc01);
    const float2 r23 = unpack2(acc23);
    const float2 r45 = unpack2(acc45);
    const float2 r67 = unpack2(acc67);
    float r[B_] = {r01.x, r01.y, r23.x, r23.y, r45.x, r45.y, r67.x, r67.y};
#pragma unroll
    for (int b = 0; b < B_; b++) {
        out[((size_t)(b * VOUT_ + v)) * COUT_ + lane] = fmaxf(r[b], 0.0f);
    }
}

// ---------------------------------------------------------------------------
// Launch. Input order: x, trans_row(unused), trans_col, trans_value, row_map,
// indices, Wd, bd, Wp, bp. Output float32 (8,16384,32).
// ---------------------------------------------------------------------------
extern "C" void kernel_launch(void* const* d_in, const int* in_sizes, int n_in,
                              void* d_out, int out_size)
{
    const float* x           = (const float*)d_in[0];
    const int*   trans_col   = (const int*)  d_in[2];
    const float* trans_value = (const float*)d_in[3];
    const int*   row_map     = (const int*)  d_in[4];
    const int*   indices     = (const int*)  d_in[5];
    const float* Wd          = (const float*)d_in[6];
    const float* bd          = (const float*)d_in[7];
    const float* Wp          = (const float*)d_in[8];
    const float* bp          = (const float*)d_in[9];
    float* out = (float*)d_out;

    pool_kernel<<<VOUT_ / 16, 256>>>(x, trans_col, trans_value, row_map);
    fused_conv_kernel<<<VOUT_ / WARPS_PER_BLOCK, 256>>>(indices, Wd, bd, Wp, bp, out);
}

// round 10
// speedup vs baseline: 3.3030x; 1.0870x over previous
#include <cuda_runtime.h>
#include <cuda_fp16.h>
#include <cstdint>

#define B_    8
#define VIN_  4096
#define CIN_  64
#define VOUT_ 16384
#define S_    9
#define COUT_ 32

// 16 MB fp16 scratch for pooled[b][v][c]
__device__ __half g_pooled_h[(size_t)B_ * VOUT_ * CIN_];

// ---------------- packed f32x2 helpers (Blackwell FFMA2) ----------------
__device__ __forceinline__ unsigned long long pack2(float lo, float hi) {
    unsigned long long r;
    asm("mov.b64 %0, {%1, %2};" : "=l"(r) : "f"(lo), "f"(hi));
    return r;
}
__device__ __forceinline__ void fma2(unsigned long long& d,
                                     unsigned long long a,
                                     unsigned long long b) {
    asm("fma.rn.f32x2 %0, %1, %2, %0;" : "+l"(d) : "l"(a), "l"(b));
}
__device__ __forceinline__ float2 unpack2(unsigned long long v) {
    float2 r;
    asm("mov.b64 {%0, %1}, %2;" : "=f"(r.x), "=f"(r.y) : "l"(v));
    return r;
}

// ---------------------------------------------------------------------------
// Kernel 1: pooled[b,v,:] = sum_{j<3} trans_value[e_j] * x[b, trans_col[e_j], :]
// fp32 math, fp16 store (halves scratch traffic both here and in kernel 2).
// ---------------------------------------------------------------------------
__global__ __launch_bounds__(256) void pool_kernel(
    const float* __restrict__ x,
    const int*   __restrict__ trans_col,
    const float* __restrict__ trans_value,
    const int*   __restrict__ row_map)
{
    __shared__ int   col_s[16][3];
    __shared__ float val_s[16][3];

    const int tid  = threadIdx.x;
    const int vloc = tid >> 4;
    const int quad = tid & 15;
    const int v    = blockIdx.x * 16 + vloc;

    if (quad < 3) {
        const int e = row_map[v * 3 + quad];
        col_s[vloc][quad] = trans_col[e];
        val_s[vloc][quad] = trans_value[e];
    }
    __syncthreads();

    const int c0 = quad * 4;
    const int col0 = col_s[vloc][0];
    const int col1 = col_s[vloc][1];
    const int col2 = col_s[vloc][2];
    const float w0 = val_s[vloc][0];
    const float w1 = val_s[vloc][1];
    const float w2 = val_s[vloc][2];

#pragma unroll
    for (int b = 0; b < B_; b++) {
        const float4 a0 = *(const float4*)(x + ((size_t)(b * VIN_ + col0)) * CIN_ + c0);
        const float4 a1 = *(const float4*)(x + ((size_t)(b * VIN_ + col1)) * CIN_ + c0);
        const float4 a2 = *(const float4*)(x + ((size_t)(b * VIN_ + col2)) * CIN_ + c0);
        float4 r;
        r.x = fmaf(w0, a0.x, fmaf(w1, a1.x, w2 * a2.x));
        r.y = fmaf(w0, a0.y, fmaf(w1, a1.y, w2 * a2.y));
        r.z = fmaf(w0, a0.z, fmaf(w1, a1.z, w2 * a2.z));
        r.w = fmaf(w0, a0.w, fmaf(w1, a1.w, w2 * a2.w));

        __half2 h01 = __floats2half2_rn(r.x, r.y);
        __half2 h23 = __floats2half2_rn(r.z, r.w);
        uint2 st;
        st.x = *(const unsigned int*)&h01;
        st.y = *(const unsigned int*)&h23;
        *(uint2*)(g_pooled_h + ((size_t)(b * VOUT_ + v)) * CIN_ + c0) = st;
    }
}

// ---------------------------------------------------------------------------
// Kernel 2: one warp per v, two phases.
//   Phase 1 (depthwise): lane owns channels (2l, 2l+1); 72 independent LDG.32
//     fp16x2 gathers (128 B/warp each), fp32 FFMA2 accumulation; results
//     transposed into dw_s[warp][c][b] (stride 12 -> aligned quads).
//   Phase 2 (pointwise): lane = output o; acc[8 b] as 4 f32x2; dw read as
//     ulonglong2 broadcasts, Wp from padded smem, FFMA2 throughout.
// ---------------------------------------------------------------------------
#define WARPS_PER_BLOCK 8
#define WP_PAD    68   // 64 + 4 pad, conflict-free LDS.128
#define DW_STRIDE 12   // floats per channel row: 48B -> aligned quads

__global__ __launch_bounds__(256, 4) void fused_conv_kernel(
    const int*   __restrict__ indices,
    const float* __restrict__ Wd,
    const float* __restrict__ bd,
    const float* __restrict__ Wp,
    const float* __restrict__ bp,
    float*       __restrict__ out)
{
    __shared__ float dw_s[WARPS_PER_BLOCK][CIN_][DW_STRIDE];  // 24 KB
    __shared__ float wp_s[COUT_][WP_PAD];                     // 8.7 KB

    const int tid  = threadIdx.x;
    const int warp = tid >> 5;
    const int lane = tid & 31;
    const int v    = blockIdx.x * WARPS_PER_BLOCK + warp;

    // cooperative load of Wp into padded smem [o][c]
    for (int i = tid; i < COUT_ * CIN_; i += 256) {
        wp_s[i >> 6][i & 63] = Wp[i];
    }

    // neighbor indices: one load per lane (<9), broadcast by shuffle
    int u_reg = 0;
    if (lane < S_) u_reg = indices[v * S_ + lane];
    int u[S_];
#pragma unroll
    for (int s = 0; s < S_; s++) u[s] = __shfl_sync(0xffffffffu, u_reg, s);

    // ---------------- Phase 1: depthwise, packed over channel pair ----------
    {
        const int ca = 2 * lane;
        unsigned long long wdp[S_];
#pragma unroll
        for (int s = 0; s < S_; s++) {
            wdp[s] = pack2(__ldg(Wd + ca * S_ + s), __ldg(Wd + (ca + 1) * S_ + s));
        }
        const unsigned long long bdp = pack2(__ldg(bd + ca), __ldg(bd + ca + 1));

#pragma unroll
        for (int half = 0; half < 2; half++) {
            unsigned long long acc[4];
#pragma unroll
            for (int j = 0; j < 4; j++) acc[j] = bdp;

#pragma unroll
            for (int j = 0; j < 4; j++) {
                const int b = half * 4 + j;
#pragma unroll
                for (int s = 0; s < S_; s++) {
                    const __half2 ph = *(const __half2*)(
                        g_pooled_h + ((size_t)(b * VOUT_ + u[s])) * CIN_ + ca);
                    const float2 pf = __half22float2(ph);
                    fma2(acc[j], wdp[s], pack2(pf.x, pf.y));
                }
            }

            // transpose into [c][b] quads
            const float2 a0 = unpack2(acc[0]);
            const float2 a1 = unpack2(acc[1]);
            const float2 a2 = unpack2(acc[2]);
            const float2 a3 = unpack2(acc[3]);
            float4 fx, fy;
            fx.x = a0.x; fx.y = a1.x; fx.z = a2.x; fx.w = a3.x;
            fy.x = a0.y; fy.y = a1.y; fy.z = a2.y; fy.w = a3.y;
            *(float4*)&dw_s[warp][ca][half * 4]     = fx;
            *(float4*)&dw_s[warp][ca + 1][half * 4] = fy;
        }
    }
    __syncthreads();   // wp_s ready + dw_s visible within warp

    // ---------------- Phase 2: pointwise, lane = output o --------------------
    const float bpo = __ldg(bp + lane);
    unsigned long long acc01 = pack2(bpo, bpo);
    unsigned long long acc23 = acc01, acc45 = acc01, acc67 = acc01;

#pragma unroll
    for (int c4 = 0; c4 < CIN_ / 4; c4++) {
        const float4 w4 = *(const float4*)&wp_s[lane][c4 * 4];
        const unsigned long long ww0 = pack2(w4.x, w4.x);
        const unsigned long long ww1 = pack2(w4.y, w4.y);
        const unsigned long long ww2 = pack2(w4.z, w4.z);
        const unsigned long long ww3 = pack2(w4.w, w4.w);

#pragma unroll
        for (int j = 0; j < 4; j++) {
            const int c = c4 * 4 + j;
            const ulonglong2 dlo = *(const ulonglong2*)&dw_s[warp][c][0]; // b0..3
            const ulonglong2 dhi = *(const ulonglong2*)&dw_s[warp][c][4]; // b4..7
            const unsigned long long w =
                (j == 0) ? ww0 : (j == 1) ? ww1 : (j == 2) ? ww2 : ww3;
            fma2(acc01, w, dlo.x);
            fma2(acc23, w, dlo.y);
            fma2(acc45, w, dhi.x);
            fma2(acc67, w, dhi.y);
        }
    }

    const float2 r01 = unpack2(acc01);
    const float2 r23 = unpack2(acc23);
    const float2 r45 = unpack2(acc45);
    const float2 r67 = unpack2(acc67);
    float r[B_] = {r01.x, r01.y, r23.x, r23.y, r45.x, r45.y, r67.x, r67.y};
#pragma unroll
    for (int b = 0; b < B_; b++) {
        out[((size_t)(b * VOUT_ + v)) * COUT_ + lane] = fmaxf(r[b], 0.0f);
    }
}

// ---------------------------------------------------------------------------
// Launch. Input order: x, trans_row(unused), trans_col, trans_value, row_map,
// indices, Wd, bd, Wp, bp. Output float32 (8,16384,32).
// ---------------------------------------------------------------------------
extern "C" void kernel_launch(void* const* d_in, const int* in_sizes, int n_in,
                              void* d_out, int out_size)
{
    const float* x           = (const float*)d_in[0];
    const int*   trans_col   = (const int*)  d_in[2];
    const float* trans_value = (const float*)d_in[3];
    const int*   row_map     = (const int*)  d_in[4];
    const int*   indices     = (const int*)  d_in[5];
    const float* Wd          = (const float*)d_in[6];
    const float* bd          = (const float*)d_in[7];
    const float* Wp          = (const float*)d_in[8];
    const float* bp          = (const float*)d_in[9];
    float* out = (float*)d_out;

    pool_kernel<<<VOUT_ / 16, 256>>>(x, trans_col, trans_value, row_map);
    fused_conv_kernel<<<VOUT_ / WARPS_PER_BLOCK, 256>>>(indices, Wd, bd, Wp, bp, out);
}

// round 13
// speedup vs baseline: 3.3309x; 1.0085x over previous
#include <cuda_runtime.h>
#include <cuda_fp16.h>
#include <cstdint>

#define B_    8
#define VIN_  4096
#define CIN_  64
#define VOUT_ 16384
#define S_    9
#define COUT_ 32

// 16 MB fp16 scratch for pooled[b][v][c]
__device__ __half g_pooled_h[(size_t)B_ * VOUT_ * CIN_];

// ---------------- packed f32x2 helpers (Blackwell FFMA2) ----------------
__device__ __forceinline__ unsigned long long pack2(float lo, float hi) {
    unsigned long long r;
    asm("mov.b64 %0, {%1, %2};" : "=l"(r) : "f"(lo), "f"(hi));
    return r;
}
__device__ __forceinline__ void fma2(unsigned long long& d,
                                     unsigned long long a,
                                     unsigned long long b) {
    asm("fma.rn.f32x2 %0, %1, %2, %0;" : "+l"(d) : "l"(a), "l"(b));
}
__device__ __forceinline__ float2 unpack2(unsigned long long v) {
    float2 r;
    asm("mov.b64 {%0, %1}, %2;" : "=f"(r.x), "=f"(r.y) : "l"(v));
    return r;
}

// mma.sync m16n8k16, f16 inputs, f32 accumulate
__device__ __forceinline__ void mma16816(float* c,
                                         uint32_t a0, uint32_t a1,
                                         uint32_t a2, uint32_t a3,
                                         uint32_t b0, uint32_t b1) {
    asm volatile(
        "mma.sync.aligned.m16n8k16.row.col.f32.f16.f16.f32 "
        "{%0,%1,%2,%3}, {%4,%5,%6,%7}, {%8,%9}, {%0,%1,%2,%3};"
        : "+f"(c[0]), "+f"(c[1]), "+f"(c[2]), "+f"(c[3])
        : "r"(a0), "r"(a1), "r"(a2), "r"(a3), "r"(b0), "r"(b1));
}

// ---------------------------------------------------------------------------
// Kernel 1: pooled[b,v,:] = sum_{j<3} trans_value[e_j] * x[b, trans_col[e_j], :]
// fp32 math, fp16 store.
// ---------------------------------------------------------------------------
__global__ __launch_bounds__(256) void pool_kernel(
    const float* __restrict__ x,
    const int*   __restrict__ trans_col,
    const float* __restrict__ trans_value,
    const int*   __restrict__ row_map)
{
    __shared__ int   col_s[16][3];
    __shared__ float val_s[16][3];

    const int tid  = threadIdx.x;
    const int vloc = tid >> 4;
    const int quad = tid & 15;
    const int v    = blockIdx.x * 16 + vloc;

    if (quad < 3) {
        const int e = row_map[v * 3 + quad];
        col_s[vloc][quad] = trans_col[e];
        val_s[vloc][quad] = trans_value[e];
    }
    __syncthreads();

    const int c0 = quad * 4;
    const int col0 = col_s[vloc][0];
    const int col1 = col_s[vloc][1];
    const int col2 = col_s[vloc][2];
    const float w0 = val_s[vloc][0];
    const float w1 = val_s[vloc][1];
    const float w2 = val_s[vloc][2];

#pragma unroll
    for (int b = 0; b < B_; b++) {
        const float4 a0 = *(const float4*)(x + ((size_t)(b * VIN_ + col0)) * CIN_ + c0);
        const float4 a1 = *(const float4*)(x + ((size_t)(b * VIN_ + col1)) * CIN_ + c0);
        const float4 a2 = *(const float4*)(x + ((size_t)(b * VIN_ + col2)) * CIN_ + c0);
        float4 r;
        r.x = fmaf(w0, a0.x, fmaf(w1, a1.x, w2 * a2.x));
        r.y = fmaf(w0, a0.y, fmaf(w1, a1.y, w2 * a2.y));
        r.z = fmaf(w0, a0.z, fmaf(w1, a1.z, w2 * a2.z));
        r.w = fmaf(w0, a0.w, fmaf(w1, a1.w, w2 * a2.w));

        __half2 h01 = __floats2half2_rn(r.x, r.y);
        __half2 h23 = __floats2half2_rn(r.z, r.w);
        uint2 st;
        st.x = *(const unsigned int*)&h01;
        st.y = *(const unsigned int*)&h23;
        *(uint2*)(g_pooled_h + ((size_t)(b * VOUT_ + v)) * CIN_ + c0) = st;
    }
}

// ---------------------------------------------------------------------------
// Kernel 2: one warp handles TILES tiles of 2 v each.
//  Phase 1 (depthwise): 144 independent fp16x2 gathers per tile, fp32 FFMA2
//    accumulation, fp16 results to dw_h[warp][row=vv*8+b][c].
//  Phase 2 (pointwise): 16x mma.sync.m16n8k16: A = dw tile [16x64] fp16,
//    B = Wp^T [64x32] fp16 from smem, f32 accum, bias + relu epilogue.
// ---------------------------------------------------------------------------
#define WARPS 8
#define TILES 2
#define V_PER_BLOCK (WARPS * TILES * 2)   // 32
#define DWPAD 72   // halves per dw row (144 B)
#define WPPAD 72   // halves per wp row

__global__ __launch_bounds__(256) void fused_conv_kernel(
    const int*   __restrict__ indices,
    const float* __restrict__ Wd,
    const float* __restrict__ bd,
    const float* __restrict__ Wp,
    const float* __restrict__ bp,
    float*       __restrict__ out)
{
    __shared__ __align__(16) __half dw_h[WARPS][16][DWPAD];  // 18 KB
    __shared__ __align__(16) __half wp_h[COUT_][WPPAD];      // 4.5 KB

    const int tid  = threadIdx.x;
    const int warp = tid >> 5;
    const int lane = tid & 31;
    const int g    = lane >> 2;   // 0..7  (MMA group id)
    const int q    = lane & 3;    // 0..3  (MMA thread-in-group)

    // cooperative fp16 convert of Wp [o][c] into smem
    for (int i = tid; i < COUT_ * CIN_; i += 256) {
        wp_h[i >> 6][i & 63] = __float2half(Wp[i]);
    }
    __syncthreads();

    // depthwise weights for this lane's channel pair (f32x2-packed)
    const int ca = 2 * lane;
    unsigned long long wdp[S_];
#pragma unroll
    for (int s = 0; s < S_; s++) {
        wdp[s] = pack2(__ldg(Wd + ca * S_ + s), __ldg(Wd + (ca + 1) * S_ + s));
    }
    const unsigned long long bdp = pack2(__ldg(bd + ca), __ldg(bd + ca + 1));

    // pointwise bias for this lane's output columns (o = nt*8 + 2q, 2q+1)
    float2 bb[4];
#pragma unroll
    for (int nt = 0; nt < 4; nt++) {
        bb[nt] = *(const float2*)(bp + nt * 8 + q * 2);
    }

    for (int t = 0; t < TILES; t++) {   // not force-unrolled
        const int v0 = blockIdx.x * V_PER_BLOCK + warp * (TILES * 2) + t * 2;

        // neighbor indices for the 2 v's (18 contiguous ints), shuffle-bcast
        int u_reg = 0;
        if (lane < 2 * S_) u_reg = indices[v0 * S_ + lane];

        // -------- Phase 1: depthwise --------
        for (int vv = 0; vv < 2; vv++) {
            int u[S_];
#pragma unroll
            for (int s = 0; s < S_; s++)
                u[s] = __shfl_sync(0xffffffffu, u_reg, vv * S_ + s);

#pragma unroll
            for (int half = 0; half < 2; half++) {
                unsigned long long acc0 = bdp, acc1 = bdp, acc2v = bdp, acc3 = bdp;
#pragma unroll
                for (int s = 0; s < S_; s++) {
                    const __half* base =
                        g_pooled_h + (size_t)u[s] * CIN_ + ca;
                    const size_t bstr = (size_t)VOUT_ * CIN_;
                    const size_t boff = (size_t)(half * 4) * bstr;
                    const float2 p0 = __half22float2(*(const __half2*)(base + boff));
                    const float2 p1 = __half22float2(*(const __half2*)(base + boff + bstr));
                    const float2 p2 = __half22float2(*(const __half2*)(base + boff + 2 * bstr));
                    const float2 p3 = __half22float2(*(const __half2*)(base + boff + 3 * bstr));
                    fma2(acc0, wdp[s], pack2(p0.x, p0.y));
                    fma2(acc1, wdp[s], pack2(p1.x, p1.y));
                    fma2(acc2v, wdp[s], pack2(p2.x, p2.y));
                    fma2(acc3, wdp[s], pack2(p3.x, p3.y));
                }
                const int r0 = vv * 8 + half * 4;
                float2 a;
                a = unpack2(acc0);  *(__half2*)&dw_h[warp][r0 + 0][ca] = __floats2half2_rn(a.x, a.y);
                a = unpack2(acc1);  *(__half2*)&dw_h[warp][r0 + 1][ca] = __floats2half2_rn(a.x, a.y);
                a = unpack2(acc2v); *(__half2*)&dw_h[warp][r0 + 2][ca] = __floats2half2_rn(a.x, a.y);
                a = unpack2(acc3);  *(__half2*)&dw_h[warp][r0 + 3][ca] = __floats2half2_rn(a.x, a.y);
            }
        }
        __syncwarp();

        // -------- Phase 2: 16x32x64 GEMM via 16x mma.sync.m16n8k16 ----------
        float acc2[4][4];
#pragma unroll
        for (int nt = 0; nt < 4; nt++) {
            acc2[nt][0] = bb[nt].x; acc2[nt][1] = bb[nt].y;
            acc2[nt][2] = bb[nt].x; acc2[nt][3] = bb[nt].y;
        }

#pragma unroll
        for (int kt = 0; kt < 4; kt++) {
            const int kk = kt * 16 + q * 2;
            // A fragment (row-major m16k16): rows g / g+8, k pairs kk / kk+8
            const uint32_t a0 = *(const uint32_t*)&dw_h[warp][g][kk];
            const uint32_t a1 = *(const uint32_t*)&dw_h[warp][g + 8][kk];
            const uint32_t a2 = *(const uint32_t*)&dw_h[warp][g][kk + 8];
            const uint32_t a3 = *(const uint32_t*)&dw_h[warp][g + 8][kk + 8];
#pragma unroll
            for (int nt = 0; nt < 4; nt++) {
                const int n = nt * 8 + g;
                // B fragment (col-major k16n8): B[k][n] = Wp[n][k]
                const uint32_t b0 = *(const uint32_t*)&wp_h[n][kk];
                const uint32_t b1 = *(const uint32_t*)&wp_h[n][kk + 8];
                mma16816(acc2[nt], a0, a1, a2, a3, b0, b1);
            }
        }

        // -------- Epilogue: relu + store. c0,c1 -> (b=g, v0); c2,c3 -> v0+1.
#pragma unroll
        for (int nt = 0; nt < 4; nt++) {
            const int o = nt * 8 + q * 2;
            float2 r0, r1;
            r0.x = fmaxf(acc2[nt][0], 0.0f);
            r0.y = fmaxf(acc2[nt][1], 0.0f);
            r1.x = fmaxf(acc2[nt][2], 0.0f);
            r1.y = fmaxf(acc2[nt][3], 0.0f);
            *(float2*)(out + ((size_t)(g * VOUT_ + v0)) * COUT_ + o)     = r0;
            *(float2*)(out + ((size_t)(g * VOUT_ + v0 + 1)) * COUT_ + o) = r1;
        }
        __syncwarp();   // protect dw_h before next tile's phase 1
    }
}

// ---------------------------------------------------------------------------
// Launch. Input order: x, trans_row(unused), trans_col, trans_value, row_map,
// indices, Wd, bd, Wp, bp. Output float32 (8,16384,32).
// ---------------------------------------------------------------------------
extern "C" void kernel_launch(void* const* d_in, const int* in_sizes, int n_in,
                              void* d_out, int out_size)
{
    const float* x           = (const float*)d_in[0];
    const int*   trans_col   = (const int*)  d_in[2];
    const float* trans_value = (const float*)d_in[3];
    const int*   row_map     = (const int*)  d_in[4];
    const int*   indices     = (const int*)  d_in[5];
    const float* Wd          = (const float*)d_in[6];
    const float* bd          = (const float*)d_in[7];
    const float* Wp          = (const float*)d_in[8];
    const float* bp          = (const float*)d_in[9];
    float* out = (float*)d_out;

    pool_kernel<<<VOUT_ / 16, 256>>>(x, trans_col, trans_value, row_map);
    fused_conv_kernel<<<VOUT_ / V_PER_BLOCK, 256>>>(indices, Wd, bd, Wp, bp, out);
}

// round 15
// speedup vs baseline: 4.9260x; 1.4788x over previous
#include <cuda_runtime.h>
#include <cuda_fp16.h>
#include <cstdint>

#define B_    8
#define VIN_  4096
#define CIN_  64
#define VOUT_ 16384
#define S_    9
#define COUT_ 32

// 16 MB fp16 scratch for pooled[b][v][c]
__device__ __half g_pooled_h[(size_t)B_ * VOUT_ * CIN_];

// ---------------- packed f32x2 helpers (Blackwell FFMA2) ----------------
__device__ __forceinline__ unsigned long long pack2(float lo, float hi) {
    unsigned long long r;
    asm("mov.b64 %0, {%1, %2};" : "=l"(r) : "f"(lo), "f"(hi));
    return r;
}
__device__ __forceinline__ void fma2(unsigned long long& d,
                                     unsigned long long a,
                                     unsigned long long b) {
    asm("fma.rn.f32x2 %0, %1, %2, %0;" : "+l"(d) : "l"(a), "l"(b));
}
__device__ __forceinline__ float2 unpack2(unsigned long long v) {
    float2 r;
    asm("mov.b64 {%0, %1}, %2;" : "=f"(r.x), "=f"(r.y) : "l"(v));
    return r;
}
__device__ __forceinline__ unsigned long long h2_to_f32x2(__half2 h) {
    const float2 f = __half22float2(h);
    return pack2(f.x, f.y);
}

// mma.sync m16n8k16, f16 inputs, f32 accumulate
__device__ __forceinline__ void mma16816(float* c,
                                         uint32_t a0, uint32_t a1,
                                         uint32_t a2, uint32_t a3,
                                         uint32_t b0, uint32_t b1) {
    asm volatile(
        "mma.sync.aligned.m16n8k16.row.col.f32.f16.f16.f32 "
        "{%0,%1,%2,%3}, {%4,%5,%6,%7}, {%8,%9}, {%0,%1,%2,%3};"
        : "+f"(c[0]), "+f"(c[1]), "+f"(c[2]), "+f"(c[3])
        : "r"(a0), "r"(a1), "r"(a2), "r"(a3), "r"(b0), "r"(b1));
}

// ---------------------------------------------------------------------------
// Kernel 1: pooled[b,v,:] = sum_{j<3} trans_value[e_j] * x[b, trans_col[e_j], :]
// fp32 math, fp16 store.
// ---------------------------------------------------------------------------
__global__ __launch_bounds__(256) void pool_kernel(
    const float* __restrict__ x,
    const int*   __restrict__ trans_col,
    const float* __restrict__ trans_value,
    const int*   __restrict__ row_map)
{
    __shared__ int   col_s[16][3];
    __shared__ float val_s[16][3];

    const int tid  = threadIdx.x;
    const int vloc = tid >> 4;
    const int quad = tid & 15;
    const int v    = blockIdx.x * 16 + vloc;

    if (quad < 3) {
        const int e = row_map[v * 3 + quad];
        col_s[vloc][quad] = trans_col[e];
        val_s[vloc][quad] = trans_value[e];
    }
    __syncthreads();

    const int c0 = quad * 4;
    const int col0 = col_s[vloc][0];
    const int col1 = col_s[vloc][1];
    const int col2 = col_s[vloc][2];
    const float w0 = val_s[vloc][0];
    const float w1 = val_s[vloc][1];
    const float w2 = val_s[vloc][2];

#pragma unroll
    for (int b = 0; b < B_; b++) {
        const float4 a0 = *(const float4*)(x + ((size_t)(b * VIN_ + col0)) * CIN_ + c0);
        const float4 a1 = *(const float4*)(x + ((size_t)(b * VIN_ + col1)) * CIN_ + c0);
        const float4 a2 = *(const float4*)(x + ((size_t)(b * VIN_ + col2)) * CIN_ + c0);
        float4 r;
        r.x = fmaf(w0, a0.x, fmaf(w1, a1.x, w2 * a2.x));
        r.y = fmaf(w0, a0.y, fmaf(w1, a1.y, w2 * a2.y));
        r.z = fmaf(w0, a0.z, fmaf(w1, a1.z, w2 * a2.z));
        r.w = fmaf(w0, a0.w, fmaf(w1, a1.w, w2 * a2.w));

        __half2 h01 = __floats2half2_rn(r.x, r.y);
        __half2 h23 = __floats2half2_rn(r.z, r.w);
        uint2 st;
        st.x = *(const unsigned int*)&h01;
        st.y = *(const unsigned int*)&h23;
        *(uint2*)(g_pooled_h + ((size_t)(b * VOUT_ + v)) * CIN_ + c0) = st;
    }
}

// ---------------------------------------------------------------------------
// Kernel 2: one warp = one 2-v tile (grid 1024).
//  Phase 1 (depthwise): 4 bursts of 36 independent fp16x2 gathers, fp32 FFMA2
//    accumulation (weights kept as half2, expanded on use), fp16 results to
//    dw_h[warp][row=vv*8+b][c].
//  Phase 2 (pointwise): 16x mma.sync.m16n8k16: A = dw tile [16x64] fp16,
//    B = Wp^T [64x32] fp16 from smem, f32 accum, bias + relu epilogue.
// ---------------------------------------------------------------------------
#define WARPS 8
#define V_PER_BLOCK (WARPS * 2)   // 16 -> grid = 1024
#define DWPAD 72   // halves per dw row (144 B, conflict-free)
#define WPPAD 72

__global__ __launch_bounds__(256, 3) void fused_conv_kernel(
    const int*   __restrict__ indices,
    const float* __restrict__ Wd,
    const float* __restrict__ bd,
    const float* __restrict__ Wp,
    const float* __restrict__ bp,
    float*       __restrict__ out)
{
    __shared__ __align__(16) __half dw_h[WARPS][16][DWPAD];  // 18 KB
    __shared__ __align__(16) __half wp_h[COUT_][WPPAD];      // 4.5 KB

    const int tid  = threadIdx.x;
    const int warp = tid >> 5;
    const int lane = tid & 31;
    const int g    = lane >> 2;   // 0..7  (MMA group id)
    const int q    = lane & 3;    // 0..3  (MMA thread-in-group)

    // cooperative fp16 convert of Wp [o][c] into smem
    for (int i = tid; i < COUT_ * CIN_; i += 256) {
        wp_h[i >> 6][i & 63] = __float2half(Wp[i]);
    }
    __syncthreads();

    // depthwise weights for this lane's channel pair, kept as half2 (1 reg each)
    const int ca = 2 * lane;
    __half2 wdh[S_];
#pragma unroll
    for (int s = 0; s < S_; s++) {
        wdh[s] = __floats2half2_rn(__ldg(Wd + ca * S_ + s),
                                   __ldg(Wd + (ca + 1) * S_ + s));
    }
    const unsigned long long bdp = pack2(__ldg(bd + ca), __ldg(bd + ca + 1));

    const int v0 = blockIdx.x * V_PER_BLOCK + warp * 2;

    // neighbor indices for the 2 v's (18 contiguous ints), shuffle-bcast,
    // kept as 32-bit half-element offsets into a b-slab
    int u_reg = 0;
    if (lane < 2 * S_) u_reg = indices[v0 * S_ + lane];
    uint32_t off[2][S_];
#pragma unroll
    for (int vv = 0; vv < 2; vv++)
#pragma unroll
        for (int s = 0; s < S_; s++)
            off[vv][s] = (uint32_t)__shfl_sync(0xffffffffu, u_reg, vv * S_ + s)
                         * CIN_ + ca;

    const size_t BSTR = (size_t)VOUT_ * CIN_;   // halves per b-slab

    // -------- Phase 1: depthwise, 4 bursts of 36 independent gathers --------
#pragma unroll
    for (int vv = 0; vv < 2; vv++) {
#pragma unroll
        for (int half = 0; half < 2; half++) {
            const __half* base = g_pooled_h + (size_t)(half * 4) * BSTR;
            unsigned long long acc0 = bdp, acc1 = bdp, acc2v = bdp, acc3 = bdp;
#pragma unroll
            for (int s = 0; s < S_; s++) {
                const __half* p = base + off[vv][s];
                const unsigned long long w = h2_to_f32x2(wdh[s]);
                fma2(acc0,  w, h2_to_f32x2(*(const __half2*)(p)));
                fma2(acc1,  w, h2_to_f32x2(*(const __half2*)(p + BSTR)));
                fma2(acc2v, w, h2_to_f32x2(*(const __half2*)(p + 2 * BSTR)));
                fma2(acc3,  w, h2_to_f32x2(*(const __half2*)(p + 3 * BSTR)));
            }
            const int r0 = vv * 8 + half * 4;
            float2 a;
            a = unpack2(acc0);  *(__half2*)&dw_h[warp][r0 + 0][ca] = __floats2half2_rn(a.x, a.y);
            a = unpack2(acc1);  *(__half2*)&dw_h[warp][r0 + 1][ca] = __floats2half2_rn(a.x, a.y);
            a = unpack2(acc2v); *(__half2*)&dw_h[warp][r0 + 2][ca] = __floats2half2_rn(a.x, a.y);
            a = unpack2(acc3);  *(__half2*)&dw_h[warp][r0 + 3][ca] = __floats2half2_rn(a.x, a.y);
        }
    }
    __syncwarp();

    // -------- Phase 2: 16x32x64 GEMM via 16x mma.sync.m16n8k16 --------------
    float acc2[4][4];
#pragma unroll
    for (int nt = 0; nt < 4; nt++) {
        const float2 bb = *(const float2*)(bp + nt * 8 + q * 2);
        acc2[nt][0] = bb.x; acc2[nt][1] = bb.y;
        acc2[nt][2] = bb.x; acc2[nt][3] = bb.y;
    }

#pragma unroll
    for (int kt = 0; kt < 4; kt++) {
        const int kk = kt * 16 + q * 2;
        // A fragment (row-major m16k16): rows g / g+8, k pairs kk / kk+8
        const uint32_t a0 = *(const uint32_t*)&dw_h[warp][g][kk];
        const uint32_t a1 = *(const uint32_t*)&dw_h[warp][g + 8][kk];
        const uint32_t a2 = *(const uint32_t*)&dw_h[warp][g][kk + 8];
        const uint32_t a3 = *(const uint32_t*)&dw_h[warp][g + 8][kk + 8];
#pragma unroll
        for (int nt = 0; nt < 4; nt++) {
            const int n = nt * 8 + g;
            // B fragment (col-major k16n8): B[k][n] = Wp[n][k]
            const uint32_t b0 = *(const uint32_t*)&wp_h[n][kk];
            const uint32_t b1 = *(const uint32_t*)&wp_h[n][kk + 8];
            mma16816(acc2[nt], a0, a1, a2, a3, b0, b1);
        }
    }

    // -------- Epilogue: relu + store. c0,c1 -> (b=g, v0); c2,c3 -> v0+1. ----
#pragma unroll
    for (int nt = 0; nt < 4; nt++) {
        const int o = nt * 8 + q * 2;
        float2 r0, r1;
        r0.x = fmaxf(acc2[nt][0], 0.0f);
        r0.y = fmaxf(acc2[nt][1], 0.0f);
        r1.x = fmaxf(acc2[nt][2], 0.0f);
        r1.y = fmaxf(acc2[nt][3], 0.0f);
        *(float2*)(out + ((size_t)(g * VOUT_ + v0)) * COUT_ + o)     = r0;
        *(float2*)(out + ((size_t)(g * VOUT_ + v0 + 1)) * COUT_ + o) = r1;
    }
}

// ---------------------------------------------------------------------------
// Launch. Input order: x, trans_row(unused), trans_col, trans_value, row_map,
// indices, Wd, bd, Wp, bp. Output float32 (8,16384,32).
// ---------------------------------------------------------------------------
extern "C" void kernel_launch(void* const* d_in, const int* in_sizes, int n_in,
                              void* d_out, int out_size)
{
    const float* x           = (const float*)d_in[0];
    const int*   trans_col   = (const int*)  d_in[2];
    const float* trans_value = (const float*)d_in[3];
    const int*   row_map     = (const int*)  d_in[4];
    const int*   indices     = (const int*)  d_in[5];
    const float* Wd          = (const float*)d_in[6];
    const float* bd          = (const float*)d_in[7];
    const float* Wp          = (const float*)d_in[8];
    const float* bp          = (const float*)d_in[9];
    float* out = (float*)d_out;

    pool_kernel<<<VOUT_ / 16, 256>>>(x, trans_col, trans_value, row_map);
    fused_conv_kernel<<<VOUT_ / V_PER_BLOCK, 256>>>(indices, Wd, bd, Wp, bp, out);
}